// round 3
// baseline (speedup 1.0000x reference)
#include <cuda_runtime.h>
#include <cuda_bf16.h>
#include <math.h>

#define NMAX 50000
#define EMAX 1000000
#define HC 256            // H*C
#define HEADS 4
#define CDIM 64
#define NEG_SLOPE 0.2f
#define BN_EPS 1e-5f

// ---------------- scratch (static device globals; no allocation) ----------------
__device__ __align__(16) float    g_x[NMAX * HC];       // projected features
__device__ __align__(16) float    g_accum[NMAX * HC];   // unnormalized weighted sum
__device__ __align__(16) int2     g_edge[EMAX];         // unpacked (src,dst) per edge
__device__ float    g_asrc[NMAX * HEADS];
__device__ float    g_adst[NMAX * HEADS];
__device__ unsigned g_segmax[NMAX * HEADS];              // ordered-uint float keys
__device__ float    g_denom[NMAX * HEADS];
__device__ float    g_csum[HC];
__device__ float    g_csumsq[HC];
__device__ int      g_is32;

// monotone float <-> unsigned key (for atomicMax on floats incl. negatives)
__device__ __forceinline__ unsigned fkey(float f) {
    unsigned u = __float_as_uint(f);
    return (u & 0x80000000u) ? ~u : (u | 0x80000000u);
}
__device__ __forceinline__ float fdec(unsigned k) {
    unsigned u = (k & 0x80000000u) ? (k & 0x7fffffffu) : ~k;
    return __uint_as_float(u);
}

__device__ __forceinline__ void red_add_v4(float* p, float4 v) {
    asm volatile("red.global.add.v4.f32 [%0], {%1,%2,%3,%4};"
                 :: "l"(p), "f"(v.x), "f"(v.y), "f"(v.z), "f"(v.w) : "memory");
}

// ---------------- kernel 0: zero accumulators ----------------
__global__ void k_init(int n) {
    int i = blockIdx.x * blockDim.x + threadIdx.x;
    if (i == 0) g_is32 = 0;
    int total = n * HC;
    for (; i < total; i += gridDim.x * blockDim.x) {
        g_accum[i] = 0.f;
        if (i < n * HEADS) { g_denom[i] = 0.f; g_segmax[i] = 0u; }
        if (i < HC) { g_csum[i] = 0.f; g_csumsq[i] = 0.f; }
    }
}

// ---------------- kernel 0b: detect edge_index dtype ----------------
// Reads the first E values as int64. This is safe in both layouts:
// E*8 bytes == the int32 buffer size (2E*4) and half the int64 buffer size.
// If the buffer is int32, pairs of int32s read as int64 are (v0 + v1*2^32),
// out of [0,N) unless v1==0 for all pairs -- detect via range check.
__global__ void k_detect(const void* ei, int E, int N) {
    int i = blockIdx.x * blockDim.x + threadIdx.x;
    const long long* p = (const long long*)ei;
    int bad = 0;
    for (; i < E; i += gridDim.x * blockDim.x) {
        long long v = p[i];
        if (v < 0 || v >= (long long)N) bad = 1;
    }
    if (__syncthreads_or(bad) && threadIdx.x == 0) g_is32 = 1;
}

// ---------------- kernel 0c: unpack edges into int2 ----------------
__global__ void k_convert(const void* ei, int E, int N) {
    int e = blockIdx.x * blockDim.x + threadIdx.x;
    if (e >= E) return;
    int s, d;
    if (g_is32) {
        const int* p = (const int*)ei;
        s = p[e]; d = p[E + e];
    } else {
        const long long* p = (const long long*)ei;
        s = (int)p[e]; d = (int)p[E + e];
    }
    // defensive clamp (no-op for valid data; prevents OOB if detection wrong)
    s = min(max(s, 0), N - 1);
    d = min(max(d, 0), N - 1);
    g_edge[e] = make_int2(s, d);
}

// ---------------- kernel 1: GEMM x = feature @ W  (M x 256 x 256) ----------------
// 64x64 tile, BK=16, 256 threads, each 4x4 micro-tile
__global__ void k_gemm(const float* __restrict__ A, const float* __restrict__ B, int M) {
    __shared__ float As[16][64];
    __shared__ float Bs[16][64];
    int tid = threadIdx.x;
    int tx = tid & 15, ty = tid >> 4;
    int rowBase = blockIdx.y * 64, colBase = blockIdx.x * 64;
    float acc[4][4] = {};
    for (int k0 = 0; k0 < 256; k0 += 16) {
        #pragma unroll
        for (int i = 0; i < 4; i++) {
            int e = tid + i * 256;
            int m = e >> 4, k = e & 15;
            float v = 0.f;
            int r = rowBase + m;
            if (r < M) v = A[(size_t)r * 256 + k0 + k];
            As[k][m] = v;
        }
        #pragma unroll
        for (int i = 0; i < 4; i++) {
            int e = tid + i * 256;
            int k = e >> 6, nn = e & 63;
            Bs[k][nn] = B[(size_t)(k0 + k) * 256 + colBase + nn];
        }
        __syncthreads();
        #pragma unroll
        for (int k = 0; k < 16; k++) {
            float a[4], b[4];
            #pragma unroll
            for (int i = 0; i < 4; i++) a[i] = As[k][ty * 4 + i];
            #pragma unroll
            for (int j = 0; j < 4; j++) b[j] = Bs[k][tx * 4 + j];
            #pragma unroll
            for (int i = 0; i < 4; i++)
                #pragma unroll
                for (int j = 0; j < 4; j++) acc[i][j] += a[i] * b[j];
        }
        __syncthreads();
    }
    #pragma unroll
    for (int i = 0; i < 4; i++) {
        int r = rowBase + ty * 4 + i;
        if (r < M) {
            #pragma unroll
            for (int j = 0; j < 4; j++)
                g_x[(size_t)r * 256 + colBase + tx * 4 + j] = acc[i][j];
        }
    }
}

// ---------------- kernel 2: per-node attention logits ----------------
// one warp per node; lane covers channels lane + 32*j
__global__ void k_attn(const float* __restrict__ att_s, const float* __restrict__ att_d, int N) {
    int warp = (blockIdx.x * blockDim.x + threadIdx.x) >> 5;
    int lane = threadIdx.x & 31;
    if (warp >= N) return;
    const float* xr = g_x + (size_t)warp * 256;
    float ss[HEADS], sd[HEADS];
    #pragma unroll
    for (int h = 0; h < HEADS; h++) {
        float as = 0.f, ad = 0.f;
        #pragma unroll
        for (int jj = 0; jj < 2; jj++) {
            int c = lane + 32 * (2 * h + jj);
            float xv = xr[c];
            as += xv * att_s[c];
            ad += xv * att_d[c];
        }
        ss[h] = as; sd[h] = ad;
    }
    #pragma unroll
    for (int h = 0; h < HEADS; h++) {
        #pragma unroll
        for (int off = 16; off; off >>= 1) {
            ss[h] += __shfl_xor_sync(0xffffffffu, ss[h], off);
            sd[h] += __shfl_xor_sync(0xffffffffu, sd[h], off);
        }
    }
    if (lane == 0) {
        #pragma unroll
        for (int h = 0; h < HEADS; h++) {
            g_asrc[warp * HEADS + h] = ss[h];
            g_adst[warp * HEADS + h] = sd[h];
        }
    }
}

// ---------------- kernel 3: edge pass A — segment max ----------------
__global__ void k_edge_max(int E, int N) {
    int e = blockIdx.x * blockDim.x + threadIdx.x;
    int total = E + N;
    if (e >= total) return;
    int s, d;
    if (e < E) { int2 sd2 = g_edge[e]; s = sd2.x; d = sd2.y; }
    else { s = d = e - E; }
    #pragma unroll
    for (int h = 0; h < HEADS; h++) {
        float v = g_asrc[s * HEADS + h] + g_adst[d * HEADS + h];
        v = v > 0.f ? v : NEG_SLOPE * v;
        atomicMax(&g_segmax[d * HEADS + h], fkey(v));
    }
}

// ---------------- kernel 4: edge pass B — exp, denom, weighted accumulate ----------------
// one warp per edge; lane handles 8 channels (2x float4)
__global__ void k_edge_accum(int E, int N) {
    int warp = (blockIdx.x * blockDim.x + threadIdx.x) >> 5;
    int lane = threadIdx.x & 31;
    int total = E + N;
    if (warp >= total) return;
    int s, d;
    if (warp < E) { int2 sd2 = g_edge[warp]; s = sd2.x; d = sd2.y; }
    else { s = d = warp - E; }

    float exv = 0.f;
    if (lane < HEADS) {
        float e = g_asrc[s * HEADS + lane] + g_adst[d * HEADS + lane];
        e = e > 0.f ? e : NEG_SLOPE * e;
        float m = fdec(g_segmax[d * HEADS + lane]);
        exv = __expf(e - m);
        atomicAdd(&g_denom[d * HEADS + lane], exv);
    }
    int c0 = lane * 8;
    int h = c0 >> 6;
    float ex = __shfl_sync(0xffffffffu, exv, h);

    const float4* xs = (const float4*)(g_x + (size_t)s * 256 + c0);
    float4 v0 = xs[0], v1 = xs[1];
    v0.x *= ex; v0.y *= ex; v0.z *= ex; v0.w *= ex;
    v1.x *= ex; v1.y *= ex; v1.z *= ex; v1.w *= ex;
    float* dst = g_accum + (size_t)d * 256 + c0;
    red_add_v4(dst, v0);
    red_add_v4(dst + 4, v1);
}

// ---------------- kernel 5: batchnorm statistics ----------------
#define NPB 256
__global__ void k_bnstats(const float* __restrict__ bias, int N) {
    int c = threadIdx.x;              // 256 channels
    int n0 = blockIdx.x * NPB;
    int n1 = min(n0 + NPB, N);
    float b = bias[c];
    int hidx = c >> 6;
    float s = 0.f, sq = 0.f;
    for (int n = n0; n < n1; n++) {
        float hval = g_accum[(size_t)n * 256 + c] / g_denom[n * HEADS + hidx] + b;
        s += hval; sq += hval * hval;
    }
    atomicAdd(&g_csum[c], s);
    atomicAdd(&g_csumsq[c], sq);
}

// ---------------- kernel 6: normalize + BN + ELU + residual ----------------
__global__ void k_final(const float* __restrict__ feature,
                        const float* __restrict__ bias,
                        const float* __restrict__ gamma,
                        const float* __restrict__ beta,
                        float* __restrict__ out, int N) {
    int i = blockIdx.x * blockDim.x + threadIdx.x;
    int total = N * HC;
    if (i >= total) return;
    int c = i & 255;
    int n = i >> 8;
    float invN = 1.f / (float)N;
    float mu = g_csum[c] * invN;
    float var = g_csumsq[c] * invN - mu * mu;
    float rstd = rsqrtf(var + BN_EPS);
    float hval = g_accum[i] / g_denom[n * HEADS + (c >> 6)] + bias[c];
    hval = (hval - mu) * rstd * gamma[c] + beta[c];
    hval = hval > 0.f ? hval : (expf(hval) - 1.f);   // ELU
    out[i] = feature[i] + hval;
}

// ---------------- launch ----------------
extern "C" void kernel_launch(void* const* d_in, const int* in_sizes, int n_in,
                              void* d_out, int out_size) {
    // ---- robust input identification by element count ----
    //   insertion order: feature, edge_index, W, att_src, att_dst, bias, gamma, beta
    //   sorted order:    W, att_dst, att_src, beta, bias, edge_index, feature, gamma
    int idx_feat = 0, idx_edge = 0, idx_W = 0;
    int small[8]; int nsmall = 0;
    long long max1 = -1, max2 = -1;
    for (int i = 0; i < n_in; i++) {
        long long s = in_sizes[i];
        if (s > max1) { max2 = max1; max1 = s; }
        else if (s > max2) { max2 = s; }
    }
    for (int i = 0; i < n_in; i++) {
        long long s = in_sizes[i];
        if (s == max1) idx_feat = i;
        else if (s == max2) idx_edge = i;
        else if (s == 65536) idx_W = i;
        else if (nsmall < 8) small[nsmall++] = i;
    }

    int i_asrc, i_adst, i_bias, i_gamma, i_beta;
    if (idx_feat == 0) {
        // insertion order: small[] = {att_src, att_dst, bias, gamma, beta}
        i_asrc = small[0]; i_adst = small[1];
        i_bias = small[2]; i_gamma = small[3]; i_beta = small[4];
    } else {
        // sorted order: small[] = {att_dst, att_src, beta, bias, gamma}
        i_adst = small[0]; i_asrc = small[1];
        i_beta = small[2]; i_bias = small[3]; i_gamma = small[4];
    }

    const float* feature = (const float*)d_in[idx_feat];
    const void*  ei      = (const void*)d_in[idx_edge];
    const float* W       = (const float*)d_in[idx_W];
    const float* att_src = (const float*)d_in[i_asrc];
    const float* att_dst = (const float*)d_in[i_adst];
    const float* bias    = (const float*)d_in[i_bias];
    const float* gamma   = (const float*)d_in[i_gamma];
    const float* beta    = (const float*)d_in[i_beta];
    float* out = (float*)d_out;

    int N = (int)(max1 / HC);
    int E = (int)(max2 / 2);
    if (E > EMAX) E = EMAX;
    int total_edges = E + N;

    // 0: zero accumulators + dtype flag
    k_init<<<2048, 256>>>(N);

    // 0b: detect edge_index dtype (int32 vs int64)
    k_detect<<<1024, 256>>>(ei, E, N);

    // 0c: unpack edges to int2
    k_convert<<<(E + 255) / 256, 256>>>(ei, E, N);

    // 1: GEMM
    dim3 gg(HC / 64, (N + 63) / 64);
    k_gemm<<<gg, 256>>>(feature, W, N);

    // 2: attention logits (warp per node)
    k_attn<<<(N * 32 + 255) / 256, 256>>>(att_src, att_dst, N);

    // 3: segment max
    k_edge_max<<<(total_edges + 255) / 256, 256>>>(E, N);

    // 4: exp + accumulate (warp per edge)
    k_edge_accum<<<(total_edges * 32 + 255) / 256, 256>>>(E, N);

    // 5: batchnorm stats
    k_bnstats<<<(N + NPB - 1) / NPB, 256>>>(bias, N);

    // 6: final fused epilogue
    k_final<<<(N * HC + 255) / 256, 256>>>(feature, bias, gamma, beta, out, N);
}

// round 4
// speedup vs baseline: 1.8197x; 1.8197x over previous
#include <cuda_runtime.h>
#include <cuda_bf16.h>
#include <math.h>

#define NMAX 50000
#define EMAX 1000000
#define HC 256            // H*C
#define HEADS 4
#define NEG_SLOPE 0.2f
#define BN_EPS 1e-5f
#define SCAN_BLOCKS 256

// ---------------- scratch (static device globals; no allocation) ----------------
__device__ __align__(16) float g_x[NMAX * HC];       // projected features
__device__ __align__(16) float g_accum[NMAX * HC];   // final h (pre-BN)
__device__ __align__(16) int2  g_edge[EMAX];         // decoded (src,dst)
__device__ int   g_srcs[EMAX];                        // CSR: src ids grouped by dst
__device__ int   g_count[NMAX];
__device__ int   g_cursor[NMAX];
__device__ int   g_rowptr[NMAX + 1];
__device__ int   g_blocksum[SCAN_BLOCKS];
__device__ float g_asrc[NMAX * HEADS];
__device__ float g_adst[NMAX * HEADS];
__device__ float g_csum[HC];
__device__ float g_csumsq[HC];
__device__ int   g_is32;

__device__ __forceinline__ float lrelu(float v) {
    return v > 0.f ? v : NEG_SLOPE * v;
}

// ---------------- kernel 0: zero small scratch ----------------
__global__ void k_init(int N) {
    int i = blockIdx.x * blockDim.x + threadIdx.x;
    if (i == 0) g_is32 = 0;
    for (; i < N; i += gridDim.x * blockDim.x) {
        g_count[i] = 0; g_cursor[i] = 0;
        if (i < HC) { g_csum[i] = 0.f; g_csumsq[i] = 0.f; }
    }
}

// ---------------- kernel 0b: detect edge_index dtype ----------------
// Read first E values as int64 (safe size in both layouts). int32 pairs read
// as int64 fall outside [0,N) unless the high word is 0 for every pair.
__global__ void k_detect(const void* ei, int E, int N) {
    int i = blockIdx.x * blockDim.x + threadIdx.x;
    const long long* p = (const long long*)ei;
    int bad = 0;
    for (; i < E; i += gridDim.x * blockDim.x) {
        long long v = p[i];
        if (v < 0 || v >= (long long)N) bad = 1;
    }
    if (__syncthreads_or(bad) && threadIdx.x == 0) g_is32 = 1;
}

// ---------------- kernel 0c: decode edges + dst histogram ----------------
__global__ void k_convert(const void* ei, int E, int N) {
    int e = blockIdx.x * blockDim.x + threadIdx.x;
    if (e >= E) return;
    int s, d;
    if (g_is32) {
        const int* p = (const int*)ei;
        s = p[e]; d = p[E + e];
    } else {
        const long long* p = (const long long*)ei;
        s = (int)p[e]; d = (int)p[E + e];
    }
    s = min(max(s, 0), N - 1);
    d = min(max(d, 0), N - 1);
    g_edge[e] = make_int2(s, d);
    atomicAdd(&g_count[d], 1);
}

// ---------------- scan: exclusive prefix sum of g_count -> g_rowptr ----------------
__global__ void k_scan1(int N, int chunk) {
    __shared__ int sh[256];
    int base = blockIdx.x * chunk;
    int i = base + threadIdx.x;
    int v = (threadIdx.x < chunk && i < N) ? g_count[i] : 0;
    sh[threadIdx.x] = v;
    __syncthreads();
    #pragma unroll
    for (int off = 1; off < 256; off <<= 1) {
        int t = (threadIdx.x >= off) ? sh[threadIdx.x - off] : 0;
        __syncthreads();
        sh[threadIdx.x] += t;
        __syncthreads();
    }
    if (threadIdx.x < chunk && i < N) g_rowptr[i] = sh[threadIdx.x] - v;
    if (threadIdx.x == 255) g_blocksum[blockIdx.x] = sh[255];
}
__global__ void k_scan2() {
    __shared__ int sh[256];
    int v = g_blocksum[threadIdx.x];
    sh[threadIdx.x] = v;
    __syncthreads();
    #pragma unroll
    for (int off = 1; off < 256; off <<= 1) {
        int t = (threadIdx.x >= off) ? sh[threadIdx.x - off] : 0;
        __syncthreads();
        sh[threadIdx.x] += t;
        __syncthreads();
    }
    g_blocksum[threadIdx.x] = sh[threadIdx.x] - v;   // exclusive
}
__global__ void k_scan3(int N, int chunk, int E) {
    int i = blockIdx.x * blockDim.x + threadIdx.x;
    if (i < N) g_rowptr[i] += g_blocksum[i / chunk];
    if (i == 0) g_rowptr[N] = E;
}

// ---------------- kernel: scatter edges into CSR ----------------
__global__ void k_scatter(int E) {
    int e = blockIdx.x * blockDim.x + threadIdx.x;
    if (e >= E) return;
    int2 sd = g_edge[e];
    int pos = g_rowptr[sd.y] + atomicAdd(&g_cursor[sd.y], 1);
    g_srcs[pos] = sd.x;
}

// ---------------- kernel 1: GEMM x = feature @ W  (M x 256 x 256) ----------------
// 128x128 tile, BK=16, 256 threads, 8x8 micro-tile, float4 LDS
__global__ void __launch_bounds__(256) k_gemm(const float* __restrict__ A,
                                              const float* __restrict__ B, int M) {
    __shared__ float As[16][128];
    __shared__ float Bs[16][128];
    int tid = threadIdx.x;
    int tx = tid & 15, ty = tid >> 4;
    int rowBase = blockIdx.y * 128, colBase = blockIdx.x * 128;
    float acc[8][8] = {};
    for (int k0 = 0; k0 < 256; k0 += 16) {
        #pragma unroll
        for (int i = 0; i < 2; i++) {
            int idx = tid + i * 256;        // 0..511
            int r = idx >> 2;               // 0..127
            int kk = (idx & 3) * 4;         // 0,4,8,12
            float4 v = make_float4(0.f, 0.f, 0.f, 0.f);
            int gr = rowBase + r;
            if (gr < M) v = *(const float4*)&A[(size_t)gr * 256 + k0 + kk];
            As[kk + 0][r] = v.x; As[kk + 1][r] = v.y;
            As[kk + 2][r] = v.z; As[kk + 3][r] = v.w;
        }
        #pragma unroll
        for (int i = 0; i < 2; i++) {
            int idx = tid + i * 256;
            int kk = idx >> 5;              // 0..15
            int nn = (idx & 31) * 4;        // 0..124
            *(float4*)&Bs[kk][nn] = *(const float4*)&B[(size_t)(k0 + kk) * 256 + colBase + nn];
        }
        __syncthreads();
        #pragma unroll
        for (int k = 0; k < 16; k++) {
            float a[8], b[8];
            *(float4*)&a[0] = *(float4*)&As[k][ty * 8];
            *(float4*)&a[4] = *(float4*)&As[k][ty * 8 + 4];
            *(float4*)&b[0] = *(float4*)&Bs[k][tx * 8];
            *(float4*)&b[4] = *(float4*)&Bs[k][tx * 8 + 4];
            #pragma unroll
            for (int i = 0; i < 8; i++)
                #pragma unroll
                for (int j = 0; j < 8; j++) acc[i][j] += a[i] * b[j];
        }
        __syncthreads();
    }
    #pragma unroll
    for (int i = 0; i < 8; i++) {
        int r = rowBase + ty * 8 + i;
        if (r < M) {
            float* dst = &g_x[(size_t)r * 256 + colBase + tx * 8];
            *(float4*)dst       = make_float4(acc[i][0], acc[i][1], acc[i][2], acc[i][3]);
            *(float4*)(dst + 4) = make_float4(acc[i][4], acc[i][5], acc[i][6], acc[i][7]);
        }
    }
}

// ---------------- kernel 2: per-node attention logits ----------------
__global__ void k_attn(const float* __restrict__ att_s, const float* __restrict__ att_d, int N) {
    int warp = (blockIdx.x * blockDim.x + threadIdx.x) >> 5;
    int lane = threadIdx.x & 31;
    if (warp >= N) return;
    const float* xr = g_x + (size_t)warp * 256;
    float ss[HEADS], sd[HEADS];
    #pragma unroll
    for (int h = 0; h < HEADS; h++) {
        float as = 0.f, ad = 0.f;
        #pragma unroll
        for (int jj = 0; jj < 2; jj++) {
            int c = lane + 32 * (2 * h + jj);
            float xv = xr[c];
            as += xv * att_s[c];
            ad += xv * att_d[c];
        }
        ss[h] = as; sd[h] = ad;
    }
    #pragma unroll
    for (int h = 0; h < HEADS; h++) {
        #pragma unroll
        for (int off = 16; off; off >>= 1) {
            ss[h] += __shfl_xor_sync(0xffffffffu, ss[h], off);
            sd[h] += __shfl_xor_sync(0xffffffffu, sd[h], off);
        }
    }
    if (lane == 0) {
        #pragma unroll
        for (int h = 0; h < HEADS; h++) {
            g_asrc[warp * HEADS + h] = ss[h];
            g_adst[warp * HEADS + h] = sd[h];
        }
    }
}

// ---------------- kernel 3: per-node softmax + weighted aggregation ----------------
// one warp per dst node; register-resident max/exp/denominator; single write of h
__global__ void __launch_bounds__(256) k_aggregate(const float* __restrict__ bias, int N) {
    int n = (blockIdx.x * blockDim.x + threadIdx.x) >> 5;
    int lane = threadIdx.x & 31;
    if (n >= N) return;
    int row0 = g_rowptr[n];
    int deg  = g_rowptr[n + 1] - row0;

    float adl[HEADS], asl[HEADS];
    #pragma unroll
    for (int h = 0; h < HEADS; h++) {
        adl[h] = g_adst[n * HEADS + h];
        asl[h] = g_asrc[n * HEADS + h];
    }
    // self-loop logit seeds the max
    float selflg[HEADS], mx[HEADS];
    #pragma unroll
    for (int h = 0; h < HEADS; h++) { selflg[h] = lrelu(asl[h] + adl[h]); mx[h] = selflg[h]; }

    // pass 1: max over incoming edges
    for (int i = lane; i < deg; i += 32) {
        int s = g_srcs[row0 + i];
        #pragma unroll
        for (int h = 0; h < HEADS; h++)
            mx[h] = fmaxf(mx[h], lrelu(g_asrc[s * HEADS + h] + adl[h]));
    }
    #pragma unroll
    for (int h = 0; h < HEADS; h++)
        #pragma unroll
        for (int off = 16; off; off >>= 1)
            mx[h] = fmaxf(mx[h], __shfl_xor_sync(0xffffffffu, mx[h], off));

    // pass 2: exp + denominator + weighted gather-accumulate
    float acc[8] = {};
    float dacc[HEADS] = {};
    int myhead = lane >> 3;                 // head of this lane's 8 channels
    for (int base = 0; base < deg; base += 32) {
        int cnt = min(32, deg - base);
        int s = 0;
        float exv[HEADS];
        if (lane < cnt) {
            s = g_srcs[row0 + base + lane];
            #pragma unroll
            for (int h = 0; h < HEADS; h++) {
                float v = lrelu(g_asrc[s * HEADS + h] + adl[h]);
                exv[h] = __expf(v - mx[h]);
                dacc[h] += exv[h];
            }
        } else {
            #pragma unroll
            for (int h = 0; h < HEADS; h++) exv[h] = 0.f;
        }
        for (int j = 0; j < cnt; j++) {
            int sj = __shfl_sync(0xffffffffu, s, j);
            float e0 = __shfl_sync(0xffffffffu, exv[0], j);
            float e1 = __shfl_sync(0xffffffffu, exv[1], j);
            float e2 = __shfl_sync(0xffffffffu, exv[2], j);
            float e3 = __shfl_sync(0xffffffffu, exv[3], j);
            float ex = myhead == 0 ? e0 : myhead == 1 ? e1 : myhead == 2 ? e2 : e3;
            const float4* xp = (const float4*)(g_x + (size_t)sj * 256 + lane * 8);
            float4 v0 = xp[0], v1 = xp[1];
            acc[0] += ex * v0.x; acc[1] += ex * v0.y; acc[2] += ex * v0.z; acc[3] += ex * v0.w;
            acc[4] += ex * v1.x; acc[5] += ex * v1.y; acc[6] += ex * v1.z; acc[7] += ex * v1.w;
        }
    }
    // reduce denominators across warp
    #pragma unroll
    for (int h = 0; h < HEADS; h++)
        #pragma unroll
        for (int off = 16; off; off >>= 1)
            dacc[h] += __shfl_xor_sync(0xffffffffu, dacc[h], off);

    // self-loop contribution
    float exself[HEADS];
    #pragma unroll
    for (int h = 0; h < HEADS; h++) exself[h] = __expf(selflg[h] - mx[h]);
    {
        float ex = exself[myhead];
        const float4* xp = (const float4*)(g_x + (size_t)n * 256 + lane * 8);
        float4 v0 = xp[0], v1 = xp[1];
        acc[0] += ex * v0.x; acc[1] += ex * v0.y; acc[2] += ex * v0.z; acc[3] += ex * v0.w;
        acc[4] += ex * v1.x; acc[5] += ex * v1.y; acc[6] += ex * v1.z; acc[7] += ex * v1.w;
    }
    float inv = 1.f / (dacc[myhead] + exself[myhead]);

    int c0 = lane * 8;
    float4 b0 = *(const float4*)&bias[c0];
    float4 b1 = *(const float4*)&bias[c0 + 4];
    float* dst = g_accum + (size_t)n * 256 + c0;
    *(float4*)dst       = make_float4(acc[0] * inv + b0.x, acc[1] * inv + b0.y,
                                      acc[2] * inv + b0.z, acc[3] * inv + b0.w);
    *(float4*)(dst + 4) = make_float4(acc[4] * inv + b1.x, acc[5] * inv + b1.y,
                                      acc[6] * inv + b1.z, acc[7] * inv + b1.w);
}

// ---------------- kernel 5: batchnorm statistics ----------------
#define NPB 256
__global__ void k_bnstats(int N) {
    int c = threadIdx.x;
    int n0 = blockIdx.x * NPB;
    int n1 = min(n0 + NPB, N);
    float s = 0.f, sq = 0.f;
    for (int n = n0; n < n1; n++) {
        float hval = g_accum[(size_t)n * 256 + c];
        s += hval; sq += hval * hval;
    }
    atomicAdd(&g_csum[c], s);
    atomicAdd(&g_csumsq[c], sq);
}

// ---------------- kernel 6: BN + ELU + residual ----------------
__global__ void k_final(const float* __restrict__ feature,
                        const float* __restrict__ gamma,
                        const float* __restrict__ beta,
                        float* __restrict__ out, int N) {
    int i = blockIdx.x * blockDim.x + threadIdx.x;
    int total = N * HC;
    if (i >= total) return;
    int c = i & 255;
    float invN = 1.f / (float)N;
    float mu = g_csum[c] * invN;
    float var = g_csumsq[c] * invN - mu * mu;
    float rstd = rsqrtf(var + BN_EPS);
    float hval = (g_accum[i] - mu) * rstd * gamma[c] + beta[c];
    hval = hval > 0.f ? hval : (expf(hval) - 1.f);
    out[i] = feature[i] + hval;
}

// ---------------- launch ----------------
extern "C" void kernel_launch(void* const* d_in, const int* in_sizes, int n_in,
                              void* d_out, int out_size) {
    //   insertion order: feature, edge_index, W, att_src, att_dst, bias, gamma, beta
    //   sorted order:    W, att_dst, att_src, beta, bias, edge_index, feature, gamma
    int idx_feat = 0, idx_edge = 0, idx_W = 0;
    int small[8]; int nsmall = 0;
    long long max1 = -1, max2 = -1;
    for (int i = 0; i < n_in; i++) {
        long long s = in_sizes[i];
        if (s > max1) { max2 = max1; max1 = s; }
        else if (s > max2) { max2 = s; }
    }
    for (int i = 0; i < n_in; i++) {
        long long s = in_sizes[i];
        if (s == max1) idx_feat = i;
        else if (s == max2) idx_edge = i;
        else if (s == 65536) idx_W = i;
        else if (nsmall < 8) small[nsmall++] = i;
    }
    int i_asrc, i_adst, i_bias, i_gamma, i_beta;
    if (idx_feat == 0) {
        i_asrc = small[0]; i_adst = small[1];
        i_bias = small[2]; i_gamma = small[3]; i_beta = small[4];
    } else {
        i_adst = small[0]; i_asrc = small[1];
        i_beta = small[2]; i_bias = small[3]; i_gamma = small[4];
    }

    const float* feature = (const float*)d_in[idx_feat];
    const void*  ei      = (const void*)d_in[idx_edge];
    const float* W       = (const float*)d_in[idx_W];
    const float* att_src = (const float*)d_in[i_asrc];
    const float* att_dst = (const float*)d_in[i_adst];
    const float* bias    = (const float*)d_in[i_bias];
    const float* gamma   = (const float*)d_in[i_gamma];
    const float* beta    = (const float*)d_in[i_beta];
    float* out = (float*)d_out;

    int N = (int)(max1 / HC);
    int E = (int)(max2 / 2);
    if (E > EMAX) E = EMAX;
    int chunk = (N + SCAN_BLOCKS - 1) / SCAN_BLOCKS;

    k_init<<<256, 256>>>(N);
    k_detect<<<1024, 256>>>(ei, E, N);
    k_convert<<<(E + 255) / 256, 256>>>(ei, E, N);
    k_scan1<<<SCAN_BLOCKS, 256>>>(N, chunk);
    k_scan2<<<1, 256>>>();
    k_scan3<<<(N + 255) / 256, 256>>>(N, chunk, E);
    k_scatter<<<(E + 255) / 256, 256>>>(E);

    dim3 gg(HC / 128, (N + 127) / 128);
    k_gemm<<<gg, 256>>>(feature, W, N);
    k_attn<<<(N * 32 + 255) / 256, 256>>>(att_src, att_dst, N);
    k_aggregate<<<(N * 32 + 255) / 256, 256>>>(bias, N);
    k_bnstats<<<(N + NPB - 1) / NPB, 256>>>(N);
    k_final<<<(N * HC + 255) / 256, 256>>>(feature, gamma, beta, out, N);
}

// round 5
// speedup vs baseline: 2.4391x; 1.3404x over previous
#include <cuda_runtime.h>
#include <cuda_bf16.h>
#include <math.h>

#define NMAX 50000
#define EMAX 1000000
#define HC 256            // H*C
#define HEADS 4
#define NEG_SLOPE 0.2f
#define BN_EPS 1e-5f
#define SCAN_BLOCKS 256

// ---------------- scratch (static device globals; no allocation) ----------------
__device__ __align__(16) float g_x[NMAX * HC];       // projected features
__device__ __align__(16) float g_accum[NMAX * HC];   // final h (pre-BN)
__device__ __align__(16) int2  g_edge[EMAX];         // decoded (src,dst)
__device__ int   g_srcs[EMAX];                        // CSR: src ids grouped by dst
__device__ int   g_count[NMAX];
__device__ int   g_cursor[NMAX];
__device__ int   g_rowptr[NMAX + 1];
__device__ int   g_blocksum[SCAN_BLOCKS];
__device__ float g_asrc[NMAX * HEADS];
__device__ float g_adst[NMAX * HEADS];
__device__ float g_csum[HC];
__device__ float g_csumsq[HC];
__device__ int   g_is32;

__device__ __forceinline__ float lrelu(float v) {
    return v > 0.f ? v : NEG_SLOPE * v;
}
__device__ __forceinline__ unsigned to_tf32(float f) {
    unsigned u;
    asm("cvt.rna.tf32.f32 %0, %1;" : "=r"(u) : "f"(f));
    return u;
}

// ---------------- kernel 0: zero small scratch ----------------
__global__ void k_init(int N) {
    int i = blockIdx.x * blockDim.x + threadIdx.x;
    if (i == 0) g_is32 = 0;
    for (; i < N; i += gridDim.x * blockDim.x) {
        g_count[i] = 0; g_cursor[i] = 0;
        if (i < HC) { g_csum[i] = 0.f; g_csumsq[i] = 0.f; }
    }
}

// ---------------- kernel 0b: detect edge_index dtype ----------------
__global__ void k_detect(const void* ei, int E, int N) {
    int i = blockIdx.x * blockDim.x + threadIdx.x;
    const long long* p = (const long long*)ei;
    int bad = 0;
    for (; i < E; i += gridDim.x * blockDim.x) {
        long long v = p[i];
        if (v < 0 || v >= (long long)N) bad = 1;
    }
    if (__syncthreads_or(bad) && threadIdx.x == 0) g_is32 = 1;
}

// ---------------- kernel 0c: decode edges + dst histogram ----------------
__global__ void k_convert(const void* ei, int E, int N) {
    int e = blockIdx.x * blockDim.x + threadIdx.x;
    if (e >= E) return;
    int s, d;
    if (g_is32) {
        const int* p = (const int*)ei;
        s = p[e]; d = p[E + e];
    } else {
        const long long* p = (const long long*)ei;
        s = (int)p[e]; d = (int)p[E + e];
    }
    s = min(max(s, 0), N - 1);
    d = min(max(d, 0), N - 1);
    g_edge[e] = make_int2(s, d);
    atomicAdd(&g_count[d], 1);
}

// ---------------- scan: exclusive prefix sum of g_count -> g_rowptr ----------------
__global__ void k_scan1(int N, int chunk) {
    __shared__ int sh[256];
    int base = blockIdx.x * chunk;
    int i = base + threadIdx.x;
    int v = (threadIdx.x < chunk && i < N) ? g_count[i] : 0;
    sh[threadIdx.x] = v;
    __syncthreads();
    #pragma unroll
    for (int off = 1; off < 256; off <<= 1) {
        int t = (threadIdx.x >= off) ? sh[threadIdx.x - off] : 0;
        __syncthreads();
        sh[threadIdx.x] += t;
        __syncthreads();
    }
    if (threadIdx.x < chunk && i < N) g_rowptr[i] = sh[threadIdx.x] - v;
    if (threadIdx.x == 255) g_blocksum[blockIdx.x] = sh[255];
}
__global__ void k_scan2() {
    __shared__ int sh[256];
    int v = g_blocksum[threadIdx.x];
    sh[threadIdx.x] = v;
    __syncthreads();
    #pragma unroll
    for (int off = 1; off < 256; off <<= 1) {
        int t = (threadIdx.x >= off) ? sh[threadIdx.x - off] : 0;
        __syncthreads();
        sh[threadIdx.x] += t;
        __syncthreads();
    }
    g_blocksum[threadIdx.x] = sh[threadIdx.x] - v;   // exclusive
}
__global__ void k_scan3(int N, int chunk, int E) {
    int i = blockIdx.x * blockDim.x + threadIdx.x;
    if (i < N) g_rowptr[i] += g_blocksum[i / chunk];
    if (i == 0) g_rowptr[N] = E;
}

// ---------------- kernel: scatter edges into CSR ----------------
__global__ void k_scatter(int E) {
    int e = blockIdx.x * blockDim.x + threadIdx.x;
    if (e >= E) return;
    int2 sd = g_edge[e];
    int pos = g_rowptr[sd.y] + atomicAdd(&g_cursor[sd.y], 1);
    g_srcs[pos] = sd.x;
}

// ---------------- kernel 1: TF32 tensor-core GEMM x = feature @ W ----------------
// 128x128 block tile, BK=32, 8 warps (4M x 2N), warp tile 32x64,
// mma.sync.m16n8k8.tf32, smem stride 136 (bank-conflict-free fragments)
#define SMS 136
__global__ void __launch_bounds__(256) k_gemm(const float* __restrict__ A,
                                              const float* __restrict__ B, int M) {
    __shared__ unsigned As[32][SMS];
    __shared__ unsigned Bs[32][SMS];
    int tid = threadIdx.x;
    int lane = tid & 31, wid = tid >> 5;
    int warpM = wid & 3;          // 0..3 -> 32 rows each
    int warpN = wid >> 2;         // 0..1 -> 64 cols each
    int tr = lane >> 2;           // 0..7
    int tc = lane & 3;            // 0..3
    int rowBase = blockIdx.y * 128, colBase = blockIdx.x * 128;

    float c[2][8][4];
    #pragma unroll
    for (int mt = 0; mt < 2; mt++)
        #pragma unroll
        for (int nt = 0; nt < 8; nt++)
            #pragma unroll
            for (int q = 0; q < 4; q++) c[mt][nt][q] = 0.f;

    for (int k0 = 0; k0 < 256; k0 += 32) {
        // load A tile: 128 rows x 32 k (tf32-converted)
        #pragma unroll
        for (int i = 0; i < 4; i++) {
            int idx = tid + i * 256;         // 0..1023
            int r = idx >> 3;                // 0..127
            int kk = (idx & 7) * 4;          // 0,4,...,28
            float4 v = make_float4(0.f, 0.f, 0.f, 0.f);
            int gr = rowBase + r;
            if (gr < M) v = *(const float4*)&A[(size_t)gr * 256 + k0 + kk];
            As[kk + 0][r] = to_tf32(v.x);
            As[kk + 1][r] = to_tf32(v.y);
            As[kk + 2][r] = to_tf32(v.z);
            As[kk + 3][r] = to_tf32(v.w);
        }
        // load B tile: 32 k x 128 n
        #pragma unroll
        for (int i = 0; i < 4; i++) {
            int idx = tid + i * 256;
            int kk = idx >> 5;               // 0..31
            int nn = (idx & 31) * 4;         // 0..124
            float4 v = *(const float4*)&B[(size_t)(k0 + kk) * 256 + colBase + nn];
            Bs[kk][nn + 0] = to_tf32(v.x);
            Bs[kk][nn + 1] = to_tf32(v.y);
            Bs[kk][nn + 2] = to_tf32(v.z);
            Bs[kk][nn + 3] = to_tf32(v.w);
        }
        __syncthreads();
        #pragma unroll
        for (int ks = 0; ks < 4; ks++) {
            int kb = ks * 8;
            unsigned a[2][4], b[8][2];
            #pragma unroll
            for (int mt = 0; mt < 2; mt++) {
                int m0 = warpM * 32 + mt * 16;
                a[mt][0] = As[kb + tc][m0 + tr];
                a[mt][1] = As[kb + tc][m0 + tr + 8];
                a[mt][2] = As[kb + tc + 4][m0 + tr];
                a[mt][3] = As[kb + tc + 4][m0 + tr + 8];
            }
            #pragma unroll
            for (int nt = 0; nt < 8; nt++) {
                int n0 = warpN * 64 + nt * 8;
                b[nt][0] = Bs[kb + tc][n0 + tr];
                b[nt][1] = Bs[kb + tc + 4][n0 + tr];
            }
            #pragma unroll
            for (int mt = 0; mt < 2; mt++)
                #pragma unroll
                for (int nt = 0; nt < 8; nt++) {
                    asm volatile(
                        "mma.sync.aligned.m16n8k8.row.col.f32.tf32.tf32.f32 "
                        "{%0,%1,%2,%3}, {%4,%5,%6,%7}, {%8,%9}, {%0,%1,%2,%3};"
                        : "+f"(c[mt][nt][0]), "+f"(c[mt][nt][1]),
                          "+f"(c[mt][nt][2]), "+f"(c[mt][nt][3])
                        : "r"(a[mt][0]), "r"(a[mt][1]), "r"(a[mt][2]), "r"(a[mt][3]),
                          "r"(b[nt][0]), "r"(b[nt][1]));
                }
        }
        __syncthreads();
    }
    // store: per (mt,nt): rows tr,tr+8; cols nt*8+2*tc,+1
    #pragma unroll
    for (int mt = 0; mt < 2; mt++) {
        int m0 = rowBase + warpM * 32 + mt * 16;
        #pragma unroll
        for (int half = 0; half < 2; half++) {
            int r = m0 + tr + half * 8;
            if (r < M) {
                float* rowp = &g_x[(size_t)r * 256 + colBase + warpN * 64];
                #pragma unroll
                for (int nt = 0; nt < 8; nt++) {
                    float2 v = make_float2(c[mt][nt][half * 2], c[mt][nt][half * 2 + 1]);
                    *(float2*)&rowp[nt * 8 + 2 * tc] = v;
                }
            }
        }
    }
}

// ---------------- kernel 2: per-node attention logits ----------------
__global__ void k_attn(const float* __restrict__ att_s, const float* __restrict__ att_d, int N) {
    int warp = (blockIdx.x * blockDim.x + threadIdx.x) >> 5;
    int lane = threadIdx.x & 31;
    if (warp >= N) return;
    const float* xr = g_x + (size_t)warp * 256;
    float ss[HEADS], sd[HEADS];
    #pragma unroll
    for (int h = 0; h < HEADS; h++) {
        float as = 0.f, ad = 0.f;
        #pragma unroll
        for (int jj = 0; jj < 2; jj++) {
            int c = lane + 32 * (2 * h + jj);
            float xv = xr[c];
            as += xv * att_s[c];
            ad += xv * att_d[c];
        }
        ss[h] = as; sd[h] = ad;
    }
    #pragma unroll
    for (int h = 0; h < HEADS; h++) {
        #pragma unroll
        for (int off = 16; off; off >>= 1) {
            ss[h] += __shfl_xor_sync(0xffffffffu, ss[h], off);
            sd[h] += __shfl_xor_sync(0xffffffffu, sd[h], off);
        }
    }
    if (lane == 0) {
        #pragma unroll
        for (int h = 0; h < HEADS; h++) {
            g_asrc[warp * HEADS + h] = ss[h];
            g_adst[warp * HEADS + h] = sd[h];
        }
    }
}

// ---------------- kernel 3: per-node softmax + weighted aggregation ----------------
__global__ void __launch_bounds__(256) k_aggregate(const float* __restrict__ bias, int N) {
    int n = (blockIdx.x * blockDim.x + threadIdx.x) >> 5;
    int lane = threadIdx.x & 31;
    if (n >= N) return;
    int row0 = g_rowptr[n];
    int deg  = g_rowptr[n + 1] - row0;

    float adl[HEADS], asl[HEADS];
    #pragma unroll
    for (int h = 0; h < HEADS; h++) {
        adl[h] = g_adst[n * HEADS + h];
        asl[h] = g_asrc[n * HEADS + h];
    }
    float selflg[HEADS], mx[HEADS];
    #pragma unroll
    for (int h = 0; h < HEADS; h++) { selflg[h] = lrelu(asl[h] + adl[h]); mx[h] = selflg[h]; }

    for (int i = lane; i < deg; i += 32) {
        int s = g_srcs[row0 + i];
        #pragma unroll
        for (int h = 0; h < HEADS; h++)
            mx[h] = fmaxf(mx[h], lrelu(g_asrc[s * HEADS + h] + adl[h]));
    }
    #pragma unroll
    for (int h = 0; h < HEADS; h++)
        #pragma unroll
        for (int off = 16; off; off >>= 1)
            mx[h] = fmaxf(mx[h], __shfl_xor_sync(0xffffffffu, mx[h], off));

    float acc[8] = {};
    float dacc[HEADS] = {};
    int myhead = lane >> 3;
    for (int base = 0; base < deg; base += 32) {
        int cnt = min(32, deg - base);
        int s = 0;
        float exv[HEADS];
        if (lane < cnt) {
            s = g_srcs[row0 + base + lane];
            #pragma unroll
            for (int h = 0; h < HEADS; h++) {
                float v = lrelu(g_asrc[s * HEADS + h] + adl[h]);
                exv[h] = __expf(v - mx[h]);
                dacc[h] += exv[h];
            }
        } else {
            #pragma unroll
            for (int h = 0; h < HEADS; h++) exv[h] = 0.f;
        }
        for (int j = 0; j < cnt; j++) {
            int sj = __shfl_sync(0xffffffffu, s, j);
            float e0 = __shfl_sync(0xffffffffu, exv[0], j);
            float e1 = __shfl_sync(0xffffffffu, exv[1], j);
            float e2 = __shfl_sync(0xffffffffu, exv[2], j);
            float e3 = __shfl_sync(0xffffffffu, exv[3], j);
            float ex = myhead == 0 ? e0 : myhead == 1 ? e1 : myhead == 2 ? e2 : e3;
            const float4* xp = (const float4*)(g_x + (size_t)sj * 256 + lane * 8);
            float4 v0 = xp[0], v1 = xp[1];
            acc[0] += ex * v0.x; acc[1] += ex * v0.y; acc[2] += ex * v0.z; acc[3] += ex * v0.w;
            acc[4] += ex * v1.x; acc[5] += ex * v1.y; acc[6] += ex * v1.z; acc[7] += ex * v1.w;
        }
    }
    #pragma unroll
    for (int h = 0; h < HEADS; h++)
        #pragma unroll
        for (int off = 16; off; off >>= 1)
            dacc[h] += __shfl_xor_sync(0xffffffffu, dacc[h], off);

    float exself[HEADS];
    #pragma unroll
    for (int h = 0; h < HEADS; h++) exself[h] = __expf(selflg[h] - mx[h]);
    {
        float ex = exself[myhead];
        const float4* xp = (const float4*)(g_x + (size_t)n * 256 + lane * 8);
        float4 v0 = xp[0], v1 = xp[1];
        acc[0] += ex * v0.x; acc[1] += ex * v0.y; acc[2] += ex * v0.z; acc[3] += ex * v0.w;
        acc[4] += ex * v1.x; acc[5] += ex * v1.y; acc[6] += ex * v1.z; acc[7] += ex * v1.w;
    }
    float inv = 1.f / (dacc[myhead] + exself[myhead]);

    int c0 = lane * 8;
    float4 b0 = *(const float4*)&bias[c0];
    float4 b1 = *(const float4*)&bias[c0 + 4];
    float* dst = g_accum + (size_t)n * 256 + c0;
    *(float4*)dst       = make_float4(acc[0] * inv + b0.x, acc[1] * inv + b0.y,
                                      acc[2] * inv + b0.z, acc[3] * inv + b0.w);
    *(float4*)(dst + 4) = make_float4(acc[4] * inv + b1.x, acc[5] * inv + b1.y,
                                      acc[6] * inv + b1.z, acc[7] * inv + b1.w);
}

// ---------------- kernel 5: batchnorm statistics ----------------
#define NPB 256
__global__ void k_bnstats(int N) {
    int c = threadIdx.x;
    int n0 = blockIdx.x * NPB;
    int n1 = min(n0 + NPB, N);
    float s = 0.f, sq = 0.f;
    for (int n = n0; n < n1; n++) {
        float hval = g_accum[(size_t)n * 256 + c];
        s += hval; sq += hval * hval;
    }
    atomicAdd(&g_csum[c], s);
    atomicAdd(&g_csumsq[c], sq);
}

// ---------------- kernel 6: BN + ELU + residual ----------------
__global__ void k_final(const float* __restrict__ feature,
                        const float* __restrict__ gamma,
                        const float* __restrict__ beta,
                        float* __restrict__ out, int N) {
    int i = blockIdx.x * blockDim.x + threadIdx.x;
    int total = N * HC;
    if (i >= total) return;
    int c = i & 255;
    float invN = 1.f / (float)N;
    float mu = g_csum[c] * invN;
    float var = g_csumsq[c] * invN - mu * mu;
    float rstd = rsqrtf(var + BN_EPS);
    float hval = (g_accum[i] - mu) * rstd * gamma[c] + beta[c];
    hval = hval > 0.f ? hval : (expf(hval) - 1.f);
    out[i] = feature[i] + hval;
}

// ---------------- launch ----------------
extern "C" void kernel_launch(void* const* d_in, const int* in_sizes, int n_in,
                              void* d_out, int out_size) {
    int idx_feat = 0, idx_edge = 0, idx_W = 0;
    int small[8]; int nsmall = 0;
    long long max1 = -1, max2 = -1;
    for (int i = 0; i < n_in; i++) {
        long long s = in_sizes[i];
        if (s > max1) { max2 = max1; max1 = s; }
        else if (s > max2) { max2 = s; }
    }
    for (int i = 0; i < n_in; i++) {
        long long s = in_sizes[i];
        if (s == max1) idx_feat = i;
        else if (s == max2) idx_edge = i;
        else if (s == 65536) idx_W = i;
        else if (nsmall < 8) small[nsmall++] = i;
    }
    int i_asrc, i_adst, i_bias, i_gamma, i_beta;
    if (idx_feat == 0) {
        i_asrc = small[0]; i_adst = small[1];
        i_bias = small[2]; i_gamma = small[3]; i_beta = small[4];
    } else {
        i_adst = small[0]; i_asrc = small[1];
        i_beta = small[2]; i_bias = small[3]; i_gamma = small[4];
    }

    const float* feature = (const float*)d_in[idx_feat];
    const void*  ei      = (const void*)d_in[idx_edge];
    const float* W       = (const float*)d_in[idx_W];
    const float* att_src = (const float*)d_in[i_asrc];
    const float* att_dst = (const float*)d_in[i_adst];
    const float* bias    = (const float*)d_in[i_bias];
    const float* gamma   = (const float*)d_in[i_gamma];
    const float* beta    = (const float*)d_in[i_beta];
    float* out = (float*)d_out;

    int N = (int)(max1 / HC);
    int E = (int)(max2 / 2);
    if (E > EMAX) E = EMAX;
    int chunk = (N + SCAN_BLOCKS - 1) / SCAN_BLOCKS;

    k_init<<<256, 256>>>(N);
    k_detect<<<1024, 256>>>(ei, E, N);
    k_convert<<<(E + 255) / 256, 256>>>(ei, E, N);
    k_scan1<<<SCAN_BLOCKS, 256>>>(N, chunk);
    k_scan2<<<1, 256>>>();
    k_scan3<<<(N + 255) / 256, 256>>>(N, chunk, E);
    k_scatter<<<(E + 255) / 256, 256>>>(E);

    dim3 gg(HC / 128, (N + 127) / 128);
    k_gemm<<<gg, 256>>>(feature, W, N);
    k_attn<<<(N * 32 + 255) / 256, 256>>>(att_src, att_dst, N);
    k_aggregate<<<(N * 32 + 255) / 256, 256>>>(bias, N);
    k_bnstats<<<(N + NPB - 1) / NPB, 256>>>(N);
    k_final<<<(N * HC + 255) / 256, 256>>>(feature, gamma, beta, out, N);
}